// round 1
// baseline (speedup 1.0000x reference)
#include <cuda_runtime.h>

#define NB 64
#define CHN 3
#define HH 256
#define WW 256
#define TAP 43
#define PADT 21                 // TAP/2
#define PW (WW + 2*PADT)        // 298
#define ROWS1 8
#define R2 64
#define LR2 (R2 + 2*PADT)       // 106

// ---------------- per-image parameters + scratch ----------------
__device__ float d_M[NB][12];       // rows 0..2 of 4x4 color matrix (row-major r*4+c)
__device__ float d_k[NB][TAP];      // per-image separable filter taps
__device__ float d_misc[NB][4];     // sigma, cx, cy, half
__device__ float d_tmp[(size_t)NB * CHN * HH * WW];  // intermediate after h-conv (50 MB)

// ---------------- setup: color matrix + filter + misc ----------------
__device__ __forceinline__ void mm4(const float* A, const float* B, float* Co) {
#pragma unroll
    for (int i = 0; i < 4; i++)
#pragma unroll
        for (int j = 0; j < 4; j++) {
            float s = 0.f;
#pragma unroll
            for (int q = 0; q < 4; q++) s += A[i*4+q] * B[q*4+j];
            Co[i*4+j] = s;
        }
}

__global__ void setup_kernel(const float* __restrict__ gates,
                             const float* __restrict__ gauss,
                             const float* __restrict__ unif,
                             const float* __restrict__ fbank) {
    int i = threadIdx.x;
    if (i >= NB) return;
    const float P = 1.0f;
    const float s3 = 0.57735026918962576f;   // 1/sqrt(3)
    const float third = 1.0f / 3.0f;
    const float* gt = gates + i * 11;
    const float* gs = gauss + i * 8;
    const float* un = unif + i * 4;

    // S @ T : diag(c,c,c,1) then brightness translation
    float b = (gt[0] < P) ? gs[0] * 0.2f : 0.0f;
    float c = (gt[1] < P) ? exp2f(gs[1] * 0.5f) : 1.0f;
    float Cm[16];
#pragma unroll
    for (int q = 0; q < 16; q++) Cm[q] = 0.f;
    Cm[0] = c; Cm[5] = c; Cm[10] = c; Cm[15] = 1.0f;
    Cm[3] = c * b; Cm[7] = c * b; Cm[11] = c * b;

    float A[16], T2[16];

    // luma flip: (I4 - 2*vv*i_lf) @ Cm,  vv[i][j] = 1/3 for i,j<3 else 0
    float ilf = (gt[2] < P) ? floorf(un[0] * 2.0f) : 0.0f;
#pragma unroll
    for (int r = 0; r < 4; r++)
#pragma unroll
        for (int cc = 0; cc < 4; cc++) {
            float vv = (r < 3 && cc < 3) ? third : 0.f;
            A[r*4+cc] = ((r == cc) ? 1.f : 0.f) - 2.f * vv * ilf;
        }
    mm4(A, Cm, T2);
#pragma unroll
    for (int q = 0; q < 16; q++) Cm[q] = T2[q];

    // hue rotation: R4 @ Cm
    float th = (gt[3] < P) ? (un[1] * 2.0f - 1.0f) * 3.14159265358979323846f : 0.0f;
    float co = cosf(th), si = sinf(th);
    // K = [[0,-s3,s3],[s3,0,-s3],[-s3,s3,0]]
    float K[9] = {0.f, -s3, s3, s3, 0.f, -s3, -s3, s3, 0.f};
#pragma unroll
    for (int r = 0; r < 4; r++)
#pragma unroll
        for (int cc = 0; cc < 4; cc++) {
            float v;
            if (r < 3 && cc < 3)
                v = (1.f - co) * third + co * ((r == cc) ? 1.f : 0.f) + si * K[r*3+cc];
            else
                v = (r == cc) ? 1.f : 0.f;
            A[r*4+cc] = v;
        }
    mm4(A, Cm, T2);
#pragma unroll
    for (int q = 0; q < 16; q++) Cm[q] = T2[q];

    // saturation: (vv + (I4 - vv)*s) @ Cm
    float ss = (gt[4] < P) ? exp2f(gs[2] * 1.0f) : 1.0f;
#pragma unroll
    for (int r = 0; r < 4; r++)
#pragma unroll
        for (int cc = 0; cc < 4; cc++) {
            float vv = (r < 3 && cc < 3) ? third : 0.f;
            float id = (r == cc) ? 1.f : 0.f;
            A[r*4+cc] = vv + (id - vv) * ss;
        }
    mm4(A, Cm, T2);
#pragma unroll
    for (int q = 0; q < 12; q++) d_M[i][q] = T2[q];   // rows 0..2

    // ---- filter: g built iteratively, k = g @ fbank ----
    const float ep0 = 10.0f / 13.0f, epo = 1.0f / 13.0f;
    float g0 = 1.f, g1 = 1.f, g2 = 1.f, g3 = 1.f;
#pragma unroll
    for (int bnd = 0; bnd < 4; bnd++) {
        float ti = (gt[5 + bnd] < P) ? exp2f(gs[3 + bnd] * 1.0f) : 1.0f;
        float t0 = 1.f, t1 = 1.f, t2 = 1.f, t3 = 1.f;
        if (bnd == 0) t0 = ti; else if (bnd == 1) t1 = ti;
        else if (bnd == 2) t2 = ti; else t3 = ti;
        float sum = ep0 * t0 * t0 + epo * (t1 * t1 + t2 * t2 + t3 * t3);
        float inv = rsqrtf(sum);
        g0 *= t0 * inv; g1 *= t1 * inv; g2 *= t2 * inv; g3 *= t3 * inv;
    }
    for (int j = 0; j < TAP; j++)
        d_k[i][j] = g0 * fbank[j] + g1 * fbank[TAP + j]
                  + g2 * fbank[2 * TAP + j] + g3 * fbank[3 * TAP + j];

    d_misc[i][0] = (gt[9] < P) ? fabsf(gs[7]) * 0.1f : 0.0f;   // sigma
    d_misc[i][1] = un[2];                                      // cx
    d_misc[i][2] = un[3];                                      // cy
    d_misc[i][3] = (gt[10] < P) ? 0.25f : 0.0f;                // size*0.5
}

// ---------------- pass1: color transform + horizontal conv ----------------
__global__ void __launch_bounds__(256) pass1_kernel(const float* __restrict__ img) {
    __shared__ float sp[CHN][ROWS1][PW + 2];   // 298 used, padded to 300
    __shared__ float Ms[12];
    __shared__ float ksm[TAP];
    const int n = blockIdx.y;
    const int y0 = blockIdx.x * ROWS1;
    const int tid = threadIdx.x;

    if (tid < 12) Ms[tid] = d_M[n][tid];
    if (tid < TAP) ksm[tid] = d_k[n][tid];
    __syncthreads();

    float M00 = Ms[0], M01 = Ms[1], M02 = Ms[2], M03 = Ms[3];
    float M10 = Ms[4], M11 = Ms[5], M12 = Ms[6], M13 = Ms[7];
    float M20 = Ms[8], M21 = Ms[9], M22 = Ms[10], M23 = Ms[11];

    const size_t baseN = (size_t)n * CHN * HH * WW;

    // load reflect-padded rows + color transform into smem
    for (int p = tid; p < ROWS1 * PW; p += 256) {
        int r = p / PW;
        int j = p - r * PW;
        int xs = j - PADT;
        xs = (xs < 0) ? -xs : ((xs >= WW) ? (2 * WW - 2 - xs) : xs);
        int y = y0 + r;
        const float* pix = img + baseN + (size_t)y * WW + xs;
        float r0 = pix[0];
        float r1 = pix[HH * WW];
        float r2 = pix[2 * HH * WW];
        sp[0][r][j] = M00 * r0 + M01 * r1 + M02 * r2 + M03;
        sp[1][r][j] = M10 * r0 + M11 * r1 + M12 * r2 + M13;
        sp[2][r][j] = M20 * r0 + M21 * r1 + M22 * r2 + M23;
    }

    float kr[TAP];
#pragma unroll
    for (int t = 0; t < TAP; t++) kr[t] = ksm[t];
    __syncthreads();

    // horizontal conv: 8 outputs per thread (register-blocked)
    const int r = tid >> 5;
    const int x0 = (tid & 31) * 8;
    const int y = y0 + r;
#pragma unroll
    for (int c = 0; c < CHN; c++) {
        float acc[8];
#pragma unroll
        for (int q = 0; q < 8; q++) acc[q] = 0.f;
#pragma unroll
        for (int t = 0; t < TAP + 7; t++) {
            float v = sp[c][r][x0 + t];
#pragma unroll
            for (int rr = 0; rr < 8; rr++) {
                int kk = t - rr;
                if (kk >= 0 && kk < TAP) acc[rr] += kr[kk] * v;
            }
        }
        float* o = d_tmp + baseN + (size_t)c * HH * WW + (size_t)y * WW + x0;
        float4 a = make_float4(acc[0], acc[1], acc[2], acc[3]);
        float4 bq = make_float4(acc[4], acc[5], acc[6], acc[7]);
        *reinterpret_cast<float4*>(o) = a;
        *reinterpret_cast<float4*>(o + 4) = bq;
    }
}

// ---------------- pass2: vertical conv + noise + cutout ----------------
__global__ void __launch_bounds__(256) pass2_kernel(const float* __restrict__ noise,
                                                    float* __restrict__ out) {
    extern __shared__ float s[];      // LR2 * WW floats
    __shared__ float ksm[TAP];
    __shared__ float ms[4];
    const int nc = blockIdx.y;        // n*3 + c
    const int n = nc / 3;
    const int y0 = blockIdx.x * R2;
    const int tid = threadIdx.x;

    if (tid < TAP) ksm[tid] = d_k[n][tid];
    if (tid < 4) ms[tid] = d_misc[n][tid];

    const size_t base = (size_t)nc * HH * WW;
    for (int p = tid; p < LR2 * WW; p += 256) {
        int row = p >> 8;
        int x = p & 255;
        int ys = y0 + row - PADT;
        ys = (ys < 0) ? -ys : ((ys >= HH) ? (2 * HH - 2 - ys) : ys);
        s[p] = d_tmp[base + (size_t)ys * WW + x];
    }
    __syncthreads();

    float kr[TAP];
#pragma unroll
    for (int t = 0; t < TAP; t++) kr[t] = ksm[t];

    const float sigma = ms[0], cx = ms[1], cy = ms[2], half = ms[3];
    const float coordx = ((float)tid + 0.5f) * (1.0f / WW);
    const bool keepx = fabsf(coordx - cx) >= half;

#pragma unroll
    for (int g = 0; g < R2 / 8; g++) {
        float acc[8];
#pragma unroll
        for (int q = 0; q < 8; q++) acc[q] = 0.f;
        const int yb = g * 8;
#pragma unroll
        for (int t = 0; t < TAP + 7; t++) {
            float v = s[(yb + t) * WW + tid];
#pragma unroll
            for (int rr = 0; rr < 8; rr++) {
                int kk = t - rr;
                if (kk >= 0 && kk < TAP) acc[rr] += kr[kk] * v;
            }
        }
#pragma unroll
        for (int rr = 0; rr < 8; rr++) {
            int y = y0 + yb + rr;
            size_t idx = base + (size_t)y * WW + tid;
            float val = acc[rr] + noise[idx] * sigma;
            float coordy = ((float)y + 0.5f) * (1.0f / HH);
            bool keep = keepx || (fabsf(coordy - cy) >= half);
            out[idx] = keep ? val : 0.0f;
        }
    }
}

// ---------------- launch ----------------
extern "C" void kernel_launch(void* const* d_in, const int* in_sizes, int n_in,
                              void* d_out, int out_size) {
    const float* images = (const float*)d_in[0];
    const float* gates  = (const float*)d_in[1];
    const float* gauss  = (const float*)d_in[2];
    const float* unif   = (const float*)d_in[3];
    const float* noise  = (const float*)d_in[4];
    const float* fbank  = (const float*)d_in[5];
    float* out = (float*)d_out;

    setup_kernel<<<1, 64>>>(gates, gauss, unif, fbank);
    pass1_kernel<<<dim3(HH / ROWS1, NB), 256>>>(images);

    cudaFuncSetAttribute(pass2_kernel, cudaFuncAttributeMaxDynamicSharedMemorySize,
                         LR2 * WW * (int)sizeof(float));
    pass2_kernel<<<dim3(HH / R2, NB * CHN), 256, LR2 * WW * sizeof(float)>>>(noise, out);
}